// round 9
// baseline (speedup 1.0000x reference)
#include <cuda_runtime.h>
#include <math.h>
#include <stdint.h>

#define B_  8
#define S_  2048
#define D_  64
#define BM  64
#define BN  64
#define NT  256
#define NQB (S_ / BM)   // 32

typedef uint32_t u32;

// smem word offsets
#define QP_O 0                    // [8kc][64r][4tig] uint4 (hi,hi+4,lo,lo+4)
#define KP_O (QP_O + 8192)
#define VP_O (KP_O + 8192)        // [8kc][64d][4tig] uint2 (V[k],V[k+4])
#define PP_O (VP_O + 4096)        // [8kc][64r][4tig] uint2 (P[c],P[c+4])
#define LS_O (PP_O + 4096)        // l exchange [2][64]
#define SM_WORDS (LS_O + 128)
#define SM_BYTES (SM_WORDS * 4)   // 98816 B -> 2 CTAs/SM

__device__ __forceinline__ u32 f2tf(float x) {
    u32 r; asm("cvt.rna.tf32.f32 %0, %1;" : "=r"(r) : "f"(x)); return r;
}
__device__ __forceinline__ void mma8(float* d, const u32* a, u32 b0, u32 b1) {
    asm volatile("mma.sync.aligned.m16n8k8.row.col.f32.tf32.tf32.f32 "
        "{%0,%1,%2,%3}, {%4,%5,%6,%7}, {%8,%9}, {%0,%1,%2,%3};"
        : "+f"(d[0]), "+f"(d[1]), "+f"(d[2]), "+f"(d[3])
        : "r"(a[0]), "r"(a[1]), "r"(a[2]), "r"(a[3]), "r"(b0), "r"(b1));
}

// Causal flash attention, mma.sync tf32 (3xtf32 QK^T, 1xtf32 PV).
// CTA = 64 q-rows (block qb), kv tiles 0..qb. 8 warps: 4 row-groups x 2 col-halves.
// Packed/swizzled smem: LDS.128 delivers full hi+lo B-fragments.
__global__ __launch_bounds__(NT, 2) void fa_mma2(
    const float* __restrict__ Q, const float* __restrict__ K,
    const float* __restrict__ V, float* __restrict__ O)
{
    extern __shared__ u32 sm[];
    const int tid  = threadIdx.x;
    const int wid  = tid >> 5;
    const int lane = tid & 31;
    const int gid  = lane >> 2;      // 0..7
    const int tig  = lane & 3;       // 0..3
    const int rw   = wid >> 1;       // row-group 0..3 (rows 16rw..16rw+15)
    const int cw   = wid & 1;        // col-half (32 kv/d cols)
    const int qb = blockIdx.x, b = blockIdx.y;
    const int qbase = qb * BM;
    const int rq   = rw * 16 + gid;  // my fragment row (and rq+8)
    const int sw   = (tig + (gid >> 1)) & 3;   // universal swizzle rotation
    const int g2   = gid >> 1;

    // ---- Q -> QP packed hi/lo (once) ----
    {
        const int qrow = tid & 63, db = (tid >> 6) * 16;
        const float4* src = (const float4*)(Q + ((size_t)(b * S_ + qbase + qrow)) * D_ + db);
        float e[16];
#pragma unroll
        for (int j = 0; j < 4; j++) { float4 x = src[j]; e[4*j]=x.x; e[4*j+1]=x.y; e[4*j+2]=x.z; e[4*j+3]=x.w; }
        const int rot = (qrow >> 1) & 3;
#pragma unroll
        for (int c = 0; c < 2; c++) {
            const int kc = (db >> 3) + c;
#pragma unroll
            for (int j = 0; j < 4; j++) {
                float h0f = e[c*8 + j], h1f = e[c*8 + j + 4];
                u32 h0 = f2tf(h0f), h1 = f2tf(h1f);
                u32 l0w = f2tf(h0f - __uint_as_float(h0));
                u32 l1w = f2tf(h1f - __uint_as_float(h1));
                *(uint4*)&sm[QP_O + kc*1024 + qrow*16 + (((j + rot) & 3) << 2)] =
                    make_uint4(h0, h1, l0w, l1w);
            }
        }
    }

    float o[4][4];
#pragma unroll
    for (int nb = 0; nb < 4; nb++)
#pragma unroll
        for (int c = 0; c < 4; c++) o[nb][c] = 0.f;
    float l0 = 0.f, l1 = 0.f;
    const int gr0 = qbase + rq, gr1 = gr0 + 8;

    // ---- prefetch mapping: thread owns K[key][db..db+15], V[key][db..db+15] ----
    const int pkey = tid & 63, pdb = (tid >> 6) * 16;
    const int ntk = qb + 1;
    float4 kf[4], vf[4];
    {
        const float4* ks = (const float4*)(K + ((size_t)(b * S_ + pkey)) * D_ + pdb);
        const float4* vs = (const float4*)(V + ((size_t)(b * S_ + pkey)) * D_ + pdb);
#pragma unroll
        for (int j = 0; j < 4; j++) { kf[j] = ks[j]; vf[j] = vs[j]; }
    }

    for (int t = 0; t < ntk; t++) {
        __syncthreads();   // MMA1/MMA2 of t-1 done with KP/VP/PP
        // ---- store prefetched K (packed hi/lo) and V (packed pairs) ----
        {
            float e[16];
#pragma unroll
            for (int j = 0; j < 4; j++) { e[4*j]=kf[j].x; e[4*j+1]=kf[j].y; e[4*j+2]=kf[j].z; e[4*j+3]=kf[j].w; }
            const int rot = (pkey >> 1) & 3;
#pragma unroll
            for (int c = 0; c < 2; c++) {
                const int kc = (pdb >> 3) + c;
#pragma unroll
                for (int j = 0; j < 4; j++) {
                    float h0f = e[c*8 + j], h1f = e[c*8 + j + 4];
                    u32 h0 = f2tf(h0f), h1 = f2tf(h1f);
                    u32 l0w = f2tf(h0f - __uint_as_float(h0));
                    u32 l1w = f2tf(h1f - __uint_as_float(h1));
                    *(uint4*)&sm[KP_O + kc*1024 + pkey*16 + (((j + rot) & 3) << 2)] =
                        make_uint4(h0, h1, l0w, l1w);
                }
            }
#pragma unroll
            for (int j = 0; j < 4; j++) { e[4*j]=vf[j].x; e[4*j+1]=vf[j].y; e[4*j+2]=vf[j].z; e[4*j+3]=vf[j].w; }
            const int kcv = pkey >> 3, tv = pkey & 3, sl = (pkey >> 2) & 1;
#pragma unroll
            for (int i = 0; i < 16; i++) {
                const int d = pdb + i;
                sm[VP_O + kcv*512 + d*8 + (((tv + (d >> 1)) & 3) << 1) + sl] = f2tf(e[i]);
            }
        }
        __syncthreads();   // tiles visible

        // ---- prefetch next tile's K/V (overlaps all compute below) ----
        if (t + 1 < ntk) {
            const float4* ks = (const float4*)(K + ((size_t)(b * S_ + (t+1) * BN + pkey)) * D_ + pdb);
            const float4* vs = (const float4*)(V + ((size_t)(b * S_ + (t+1) * BN + pkey)) * D_ + pdb);
#pragma unroll
            for (int j = 0; j < 4; j++) { kf[j] = ks[j]; vf[j] = vs[j]; }
        }

        // ---- MMA1: S = Q @ K^T (3xtf32) ----
        float s[4][4];
#pragma unroll
        for (int nb = 0; nb < 4; nb++)
#pragma unroll
            for (int c = 0; c < 4; c++) s[nb][c] = 0.f;
#pragma unroll
        for (int kc = 0; kc < 8; kc++) {
            uint4 qa = *(const uint4*)&sm[QP_O + kc*1024 + rq*16 + (sw << 2)];
            uint4 qc = *(const uint4*)&sm[QP_O + kc*1024 + (rq+8)*16 + (sw << 2)];
            u32 ah[4] = { qa.x, qc.x, qa.y, qc.y };
            u32 al[4] = { qa.z, qc.z, qa.w, qc.w };
#pragma unroll
            for (int nb = 0; nb < 4; nb++) {
                const int key = cw * 32 + nb * 8 + gid;
                uint4 kb = *(const uint4*)&sm[KP_O + kc*1024 + key*16 + (sw << 2)];
                mma8(s[nb], ah, kb.x, kb.y);
                mma8(s[nb], al, kb.x, kb.y);
                mma8(s[nb], ah, kb.z, kb.w);
            }
        }

        // ---- exp (+ causal mask on diagonal tile), l accum, P -> PP ----
        const bool diag = (t == ntk - 1);
#pragma unroll
        for (int nb = 0; nb < 4; nb++) {
            const int cg = t * BN + cw * 32 + nb * 8 + 2 * tig;
            float p0, p1, p2, p3;
            if (diag) {
                p0 = (cg     <= gr0) ? __expf(s[nb][0]) : 0.f;
                p1 = (cg + 1 <= gr0) ? __expf(s[nb][1]) : 0.f;
                p2 = (cg     <= gr1) ? __expf(s[nb][2]) : 0.f;
                p3 = (cg + 1 <= gr1) ? __expf(s[nb][3]) : 0.f;
            } else {
                p0 = __expf(s[nb][0]); p1 = __expf(s[nb][1]);
                p2 = __expf(s[nb][2]); p3 = __expf(s[nb][3]);
            }
            l0 += p0 + p1;
            l1 += p2 + p3;
            const int base = PP_O + (cw * 4 + nb) * 512;
            const int w0 = ((((2*tig) & 3) + g2) & 3) * 2 + (tig >> 1);
            const int w1 = ((((2*tig+1) & 3) + g2) & 3) * 2 + (tig >> 1);
            sm[base + rq*8 + w0]       = f2tf(p0);
            sm[base + rq*8 + w1]       = f2tf(p1);
            sm[base + (rq+8)*8 + w0]   = f2tf(p2);
            sm[base + (rq+8)*8 + w1]   = f2tf(p3);
        }
        asm volatile("bar.sync %0, %1;" :: "r"(rw + 1), "r"(64) : "memory");

        // ---- MMA2: O += P @ V ----
#pragma unroll
        for (int kc = 0; kc < 8; kc++) {
            uint2 pa = *(const uint2*)&sm[PP_O + kc*512 + rq*8 + (sw << 1)];
            uint2 pc = *(const uint2*)&sm[PP_O + kc*512 + (rq+8)*8 + (sw << 1)];
            u32 a[4] = { pa.x, pc.x, pa.y, pc.y };
#pragma unroll
            for (int nb = 0; nb < 4; nb++) {
                const int d = cw * 32 + nb * 8 + gid;
                uint2 vb = *(const uint2*)&sm[VP_O + kc*512 + d*8 + (sw << 1)];
                mma8(o[nb], a, vb.x, vb.y);
            }
        }
    }

    // ---- epilogue: reduce l (quad + cross-col-warp), normalize, store ----
    l0 += __shfl_xor_sync(0xffffffffu, l0, 1);
    l0 += __shfl_xor_sync(0xffffffffu, l0, 2);
    l1 += __shfl_xor_sync(0xffffffffu, l1, 1);
    l1 += __shfl_xor_sync(0xffffffffu, l1, 2);
    if (tig == 0) {
        sm[LS_O + cw*64 + rq]     = __float_as_uint(l0);
        sm[LS_O + cw*64 + rq + 8] = __float_as_uint(l1);
    }
    __syncthreads();
    const float lt0 = __uint_as_float(sm[LS_O + rq])     + __uint_as_float(sm[LS_O + 64 + rq]);
    const float lt1 = __uint_as_float(sm[LS_O + rq + 8]) + __uint_as_float(sm[LS_O + 64 + rq + 8]);
    const float inv0 = 1.f / lt0, inv1 = 1.f / lt1;
    float* og0 = O + ((size_t)(b * S_ + gr0)) * D_;
    float* og1 = O + ((size_t)(b * S_ + gr1)) * D_;
#pragma unroll
    for (int nb = 0; nb < 4; nb++) {
        const int col = cw * 32 + nb * 8 + 2 * tig;
        *(float2*)(og0 + col) = make_float2(o[nb][0] * inv0, o[nb][1] * inv0);
        *(float2*)(og1 + col) = make_float2(o[nb][2] * inv1, o[nb][3] * inv1);
    }
}

extern "C" void kernel_launch(void* const* d_in, const int* in_sizes, int n_in,
                              void* d_out, int out_size) {
    const float* q = (const float*)d_in[0];
    const float* k = (const float*)d_in[1];
    const float* v = (const float*)d_in[2];
    float* o = (float*)d_out;
    cudaFuncSetAttribute(fa_mma2, cudaFuncAttributeMaxDynamicSharedMemorySize, SM_BYTES);
    dim3 grid(NQB, B_);   // 32 x 8 = 256 CTAs, 2/SM
    fa_mma2<<<grid, NT, SM_BYTES>>>(q, k, v, o);
}

// round 11
// speedup vs baseline: 1.0410x; 1.0410x over previous
#include <cuda_runtime.h>
#include <math.h>
#include <stdint.h>

#define B_  8
#define S_  2048
#define D_  64
#define BM  64
#define BN  64
#define NT  256
#define NQB (S_ / BM)   // 32

typedef uint32_t u32;

// smem word offsets
#define QP_O 0                    // [8kc][64r][4tig] uint4 (hi,hi+4,lo,lo+4)
#define KP_O (QP_O + 8192)
#define VP_O (KP_O + 8192)        // [8kcv][64d][8] packed uint2 (V[k],V[k+4])
#define LS_O (VP_O + 4096)        // l exchange [2][64]
#define OX_O QP_O                 // epilogue partial-O exchange (aliases QP)
#define SM_WORDS (LS_O + 128)
#define SM_BYTES (SM_WORDS * 4)   // 82432 B -> 2 CTAs/SM

__device__ __forceinline__ u32 f2tf(float x) {
    u32 r; asm("cvt.rna.tf32.f32 %0, %1;" : "=r"(r) : "f"(x)); return r;
}
__device__ __forceinline__ void mma8(float* d, const u32* a, u32 b0, u32 b1) {
    asm volatile("mma.sync.aligned.m16n8k8.row.col.f32.tf32.tf32.f32 "
        "{%0,%1,%2,%3}, {%4,%5,%6,%7}, {%8,%9}, {%0,%1,%2,%3};"
        : "+f"(d[0]), "+f"(d[1]), "+f"(d[2]), "+f"(d[3])
        : "r"(a[0]), "r"(a[1]), "r"(a[2]), "r"(a[3]), "r"(b0), "r"(b1));
}

// Causal flash attention, mma.sync tf32 (3xtf32 QK^T, 1xtf32 PV).
// CTA = 64 q-rows, kv tiles 0..qb. 8 warps: 4 row-groups x 2 key-halves.
// P never touches smem: split-k MMA2 + shfl fragment transpose.
__global__ __launch_bounds__(NT, 2) void fa_mma3(
    const float* __restrict__ Q, const float* __restrict__ K,
    const float* __restrict__ V, float* __restrict__ O)
{
    extern __shared__ u32 sm[];
    const int tid  = threadIdx.x;
    const int wid  = tid >> 5;
    const int lane = tid & 31;
    const int gid  = lane >> 2;      // 0..7
    const int tig  = lane & 3;       // 0..3
    const int rw   = wid >> 1;       // row-group (rows 16rw..16rw+15)
    const int cw   = wid & 1;        // key-half (32 keys)
    const int qb = blockIdx.x, b = blockIdx.y;
    const int qbase = qb * BM;
    const int rq   = rw * 16 + gid;
    const int sw   = (tig + (gid >> 1)) & 3;
    const int srcA = (lane & ~3) | (tig >> 1);
    const int srcB = srcA + 2;
    const u32 comp = tig & 1;

    // ---- Q -> QP packed hi/lo (once) ----
    {
        const int qrow = tid & 63, db = (tid >> 6) * 16;
        const float4* src = (const float4*)(Q + ((size_t)(b * S_ + qbase + qrow)) * D_ + db);
        float e[16];
#pragma unroll
        for (int j = 0; j < 4; j++) { float4 x = src[j]; e[4*j]=x.x; e[4*j+1]=x.y; e[4*j+2]=x.z; e[4*j+3]=x.w; }
        const int rot = (qrow >> 1) & 3;
#pragma unroll
        for (int c = 0; c < 2; c++) {
            const int kc = (db >> 3) + c;
#pragma unroll
            for (int j = 0; j < 4; j++) {
                float h0f = e[c*8 + j], h1f = e[c*8 + j + 4];
                u32 h0 = f2tf(h0f), h1 = f2tf(h1f);
                u32 l0w = f2tf(h0f - __uint_as_float(h0));
                u32 l1w = f2tf(h1f - __uint_as_float(h1));
                *(uint4*)&sm[QP_O + kc*1024 + qrow*16 + (((j + rot) & 3) << 2)] =
                    make_uint4(h0, h1, l0w, l1w);
            }
        }
    }

    float o[8][4];
#pragma unroll
    for (int nb = 0; nb < 8; nb++)
#pragma unroll
        for (int c = 0; c < 4; c++) o[nb][c] = 0.f;
    float l0 = 0.f, l1 = 0.f;
    const int gr0 = qbase + rq, gr1 = gr0 + 8;

    const int pkey = tid & 63, pdb = (tid >> 6) * 16;
    const int ntk = qb + 1;
    float4 vf[4];
    {
        const float4* vs = (const float4*)(V + ((size_t)(b * S_ + pkey)) * D_ + pdb);
#pragma unroll
        for (int j = 0; j < 4; j++) vf[j] = vs[j];
    }

    for (int t = 0; t < ntk; t++) {
        __syncthreads();   // MMA1/MMA2 of t-1 done with KP/VP
        // ---- K: load + pack hi/lo; V: store prefetched ----
        {
            const float4* ks = (const float4*)(K + ((size_t)(b * S_ + t * BN + pkey)) * D_ + pdb);
            float4 kf[4];
#pragma unroll
            for (int j = 0; j < 4; j++) kf[j] = ks[j];
            float e[16];
#pragma unroll
            for (int j = 0; j < 4; j++) { e[4*j]=kf[j].x; e[4*j+1]=kf[j].y; e[4*j+2]=kf[j].z; e[4*j+3]=kf[j].w; }
            const int rot = (pkey >> 1) & 3;
#pragma unroll
            for (int c = 0; c < 2; c++) {
                const int kc = (pdb >> 3) + c;
#pragma unroll
                for (int j = 0; j < 4; j++) {
                    float h0f = e[c*8 + j], h1f = e[c*8 + j + 4];
                    u32 h0 = f2tf(h0f), h1 = f2tf(h1f);
                    u32 l0w = f2tf(h0f - __uint_as_float(h0));
                    u32 l1w = f2tf(h1f - __uint_as_float(h1));
                    *(uint4*)&sm[KP_O + kc*1024 + pkey*16 + (((j + rot) & 3) << 2)] =
                        make_uint4(h0, h1, l0w, l1w);
                }
            }
#pragma unroll
            for (int j = 0; j < 4; j++) { e[4*j]=vf[j].x; e[4*j+1]=vf[j].y; e[4*j+2]=vf[j].z; e[4*j+3]=vf[j].w; }
            const int kcv = pkey >> 3, tv = pkey & 3, sl = (pkey >> 2) & 1;
#pragma unroll
            for (int i = 0; i < 16; i++) {
                const int d = pdb + i;
                sm[VP_O + kcv*512 + d*8 + (((tv + (d >> 1)) & 3) << 1) + sl] = f2tf(e[i]);
            }
        }
        __syncthreads();   // tiles visible

        // ---- prefetch next V (overlaps compute) ----
        if (t + 1 < ntk) {
            const float4* vs = (const float4*)(V + ((size_t)(b * S_ + (t+1) * BN + pkey)) * D_ + pdb);
#pragma unroll
            for (int j = 0; j < 4; j++) vf[j] = vs[j];
        }

        // ---- MMA1: S = Q @ K^T (3xtf32), warp covers its 32-key half ----
        float s[4][4];
#pragma unroll
        for (int nb = 0; nb < 4; nb++)
#pragma unroll
            for (int c = 0; c < 4; c++) s[nb][c] = 0.f;
#pragma unroll
        for (int kc = 0; kc < 8; kc++) {
            uint4 qa = *(const uint4*)&sm[QP_O + kc*1024 + rq*16 + (sw << 2)];
            uint4 qc = *(const uint4*)&sm[QP_O + kc*1024 + (rq+8)*16 + (sw << 2)];
            u32 ah[4] = { qa.x, qc.x, qa.y, qc.y };
            u32 al[4] = { qa.z, qc.z, qa.w, qc.w };
#pragma unroll
            for (int nb = 0; nb < 4; nb++) {
                const int key = cw * 32 + nb * 8 + gid;
                uint4 kb = *(const uint4*)&sm[KP_O + kc*1024 + key*16 + (sw << 2)];
                mma8(s[nb], ah, kb.x, kb.y);
                mma8(s[nb], al, kb.x, kb.y);
                mma8(s[nb], ah, kb.z, kb.w);
            }
        }

        // ---- exp (+ causal mask on diagonal tile), l accumulation ----
        const bool diag = (t == ntk - 1);
#pragma unroll
        for (int nb = 0; nb < 4; nb++) {
            const int cg = t * BN + cw * 32 + nb * 8 + 2 * tig;
            float p0, p1, p2, p3;
            if (diag) {
                p0 = (cg     <= gr0) ? __expf(s[nb][0]) : 0.f;
                p1 = (cg + 1 <= gr0) ? __expf(s[nb][1]) : 0.f;
                p2 = (cg     <= gr1) ? __expf(s[nb][2]) : 0.f;
                p3 = (cg + 1 <= gr1) ? __expf(s[nb][3]) : 0.f;
            } else {
                p0 = __expf(s[nb][0]); p1 = __expf(s[nb][1]);
                p2 = __expf(s[nb][2]); p3 = __expf(s[nb][3]);
            }
            l0 += p0 + p1;
            l1 += p2 + p3;
            s[nb][0] = p0; s[nb][1] = p1; s[nb][2] = p2; s[nb][3] = p3;
        }

        // ---- MMA2: O += P @ V over this warp's key-half; P via shfl transpose ----
#pragma unroll
        for (int kc = 0; kc < 4; kc++) {
            u32 u0 = f2tf(s[kc][0]), u1 = f2tf(s[kc][1]);
            u32 u2 = f2tf(s[kc][2]), u3 = f2tf(s[kc][3]);
            u32 x0 = __shfl_sync(0xffffffffu, u0, srcA);
            u32 x1 = __shfl_sync(0xffffffffu, u1, srcA);
            u32 x2 = __shfl_sync(0xffffffffu, u2, srcA);
            u32 x3 = __shfl_sync(0xffffffffu, u3, srcA);
            u32 y0 = __shfl_sync(0xffffffffu, u0, srcB);
            u32 y1 = __shfl_sync(0xffffffffu, u1, srcB);
            u32 y2 = __shfl_sync(0xffffffffu, u2, srcB);
            u32 y3 = __shfl_sync(0xffffffffu, u3, srcB);
            u32 a[4];
            a[0] = comp ? x1 : x0;   // P[rq][kcol tig]
            a[1] = comp ? x3 : x2;   // P[rq+8][tig]
            a[2] = comp ? y1 : y0;   // P[rq][tig+4]
            a[3] = comp ? y3 : y2;   // P[rq+8][tig+4]
            const int kcg = cw * 4 + kc;
#pragma unroll
            for (int nb = 0; nb < 8; nb++) {
                const int d = nb * 8 + gid;
                uint2 vb = *(const uint2*)&sm[VP_O + kcg*512 + d*8 + (sw << 1)];
                mma8(o[nb], a, vb.x, vb.y);
            }
        }
    }

    // ---- epilogue: reduce l + partial O across key-halves, store ----
    l0 += __shfl_xor_sync(0xffffffffu, l0, 1);
    l0 += __shfl_xor_sync(0xffffffffu, l0, 2);
    l1 += __shfl_xor_sync(0xffffffffu, l1, 1);
    l1 += __shfl_xor_sync(0xffffffffu, l1, 2);
    __syncthreads();   // everyone done with QP (OX aliases it)
    if (tig == 0) {
        sm[LS_O + cw*64 + rq]     = __float_as_uint(l0);
        sm[LS_O + cw*64 + rq + 8] = __float_as_uint(l1);
    }
    if (cw == 1) {
#pragma unroll
        for (int nb = 0; nb < 8; nb++) {
            const int col = nb * 8 + 2 * tig;
            *(float2*)&sm[OX_O + rq*64 + col]     = make_float2(o[nb][0], o[nb][1]);
            *(float2*)&sm[OX_O + (rq+8)*64 + col] = make_float2(o[nb][2], o[nb][3]);
        }
    }
    __syncthreads();
    if (cw == 0) {
        const float lt0 = __uint_as_float(sm[LS_O + rq])     + __uint_as_float(sm[LS_O + 64 + rq]);
        const float lt1 = __uint_as_float(sm[LS_O + rq + 8]) + __uint_as_float(sm[LS_O + 64 + rq + 8]);
        const float inv0 = 1.f / lt0, inv1 = 1.f / lt1;
        float* og0 = O + ((size_t)(b * S_ + gr0)) * D_;
        float* og1 = O + ((size_t)(b * S_ + gr1)) * D_;
#pragma unroll
        for (int nb = 0; nb < 8; nb++) {
            const int col = nb * 8 + 2 * tig;
            float2 w0 = *(const float2*)&sm[OX_O + rq*64 + col];
            float2 w1 = *(const float2*)&sm[OX_O + (rq+8)*64 + col];
            *(float2*)(og0 + col) = make_float2((o[nb][0] + w0.x) * inv0, (o[nb][1] + w0.y) * inv0);
            *(float2*)(og1 + col) = make_float2((o[nb][2] + w1.x) * inv1, (o[nb][3] + w1.y) * inv1);
        }
    }
}

extern "C" void kernel_launch(void* const* d_in, const int* in_sizes, int n_in,
                              void* d_out, int out_size) {
    const float* q = (const float*)d_in[0];
    const float* k = (const float*)d_in[1];
    const float* v = (const float*)d_in[2];
    float* o = (float*)d_out;
    cudaFuncSetAttribute(fa_mma3, cudaFuncAttributeMaxDynamicSharedMemorySize, SM_BYTES);
    dim3 grid(NQB, B_);   // 32 x 8 = 256 CTAs, 2/SM
    fa_mma3<<<grid, NT, SM_BYTES>>>(q, k, v, o);
}

// round 12
// speedup vs baseline: 1.7943x; 1.7236x over previous
#include <cuda_runtime.h>
#include <math.h>
#include <stdint.h>

#define B_  8
#define S_  2048
#define D_  64
#define BM  64
#define BN  64
#define NT  256
#define NQB (S_ / BM)   // 32
#define CW  8           // kv tiles per chunk
#define NCHUNK 80       // chunks per batch

typedef uint32_t u32;

// smem word offsets
#define QP_O 0                    // [8kc][64r][4tig] uint4 (hi,hi+4,lo,lo+4)
#define KP_O (QP_O + 8192)
#define VP_O (KP_O + 8192)        // [8kcv][64d][8] packed uint2 (V[k],V[k+4])
#define SM_WORDS (VP_O + 4096)
#define SM_BYTES (SM_WORDS * 4)   // 81920 B -> 2 CTAs/SM

__device__ float g_Lsum[B_ * S_];   // per-row partial softmax denominators

__device__ __forceinline__ u32 f2tf(float x) {
    u32 r; asm("cvt.rna.tf32.f32 %0, %1;" : "=r"(r) : "f"(x)); return r;
}
__device__ __forceinline__ void mma8(float* d, const u32* a, u32 b0, u32 b1) {
    asm volatile("mma.sync.aligned.m16n8k8.row.col.f32.tf32.tf32.f32 "
        "{%0,%1,%2,%3}, {%4,%5,%6,%7}, {%8,%9}, {%0,%1,%2,%3};"
        : "+f"(d[0]), "+f"(d[1]), "+f"(d[2]), "+f"(d[3])
        : "r"(a[0]), "r"(a[1]), "r"(a[2]), "r"(a[3]), "r"(b0), "r"(b1));
}

__global__ void zero_k(float* __restrict__ out, int n4) {
    int i = blockIdx.x * blockDim.x + threadIdx.x;
    if (i < n4) ((float4*)out)[i] = make_float4(0.f, 0.f, 0.f, 0.f);
    if (i < (B_ * S_) / 4) ((float4*)g_Lsum)[i] = make_float4(0.f, 0.f, 0.f, 0.f);
}

__global__ void norm_k(float* __restrict__ out, int n4) {
    int i = blockIdx.x * blockDim.x + threadIdx.x;
    if (i >= n4) return;
    float inv = 1.f / g_Lsum[i >> 4];   // 16 float4 per 64-col row
    float4 v = ((float4*)out)[i];
    v.x *= inv; v.y *= inv; v.z *= inv; v.w *= inv;
    ((float4*)out)[i] = v;
}

// Causal flash attention, mma.sync tf32 (3xtf32 QK^T, 1xtf32 PV), split-K chunks.
// CTA = (batch, 64-row q-block, kv-chunk of <=8 tiles). Raw-exp partials combine
// linearly: O/l accumulated with atomicAdd, normalized by norm_k afterwards.
__global__ __launch_bounds__(NT, 2) void fa_chunk(
    const float* __restrict__ Q, const float* __restrict__ K,
    const float* __restrict__ V, float* __restrict__ O)
{
    extern __shared__ u32 sm[];
    const int tid  = threadIdx.x;
    const int lane = tid & 31;
    const int gid  = lane >> 2;
    const int tig  = lane & 3;
    const int rw   = (tid >> 5) >> 1;     // row-group
    const int cw   = (tid >> 5) & 1;      // key-half
    const int b    = blockIdx.y;

    // ---- decode (qb, chunk) from flat index ----
    int qb, c;
    {
        const int i = blockIdx.x;
        if (i < 8)       { qb = i; c = 0; }
        else if (i < 24) { int j = i - 8;  qb = 8  + (j >> 1); c = j & 1; }
        else if (i < 48) { int j = i - 24; qb = 16 + j / 3;    c = j - 3 * (j / 3); }
        else             { int j = i - 48; qb = 24 + (j >> 2); c = j & 3; }
    }
    const int t0 = c * CW;
    const int t1 = min(t0 + CW, qb + 1);
    const int qbase = qb * BM;
    const int rq   = rw * 16 + gid;
    const int sw   = (tig + (gid >> 1)) & 3;
    const int srcA = (lane & ~3) | (tig >> 1);
    const int srcB = srcA + 2;
    const u32 comp = tig & 1;

    // ---- Q -> QP packed hi/lo ----
    {
        const int qrow = tid & 63, db = (tid >> 6) * 16;
        const float4* src = (const float4*)(Q + ((size_t)(b * S_ + qbase + qrow)) * D_ + db);
        float e[16];
#pragma unroll
        for (int j = 0; j < 4; j++) { float4 x = src[j]; e[4*j]=x.x; e[4*j+1]=x.y; e[4*j+2]=x.z; e[4*j+3]=x.w; }
        const int rot = (qrow >> 1) & 3;
#pragma unroll
        for (int cc = 0; cc < 2; cc++) {
            const int kc = (db >> 3) + cc;
#pragma unroll
            for (int j = 0; j < 4; j++) {
                float h0f = e[cc*8 + j], h1f = e[cc*8 + j + 4];
                u32 h0 = f2tf(h0f), h1 = f2tf(h1f);
                u32 l0w = f2tf(h0f - __uint_as_float(h0));
                u32 l1w = f2tf(h1f - __uint_as_float(h1));
                *(uint4*)&sm[QP_O + kc*1024 + qrow*16 + (((j + rot) & 3) << 2)] =
                    make_uint4(h0, h1, l0w, l1w);
            }
        }
    }

    float o[8][4];
#pragma unroll
    for (int nb = 0; nb < 8; nb++)
#pragma unroll
        for (int cc = 0; cc < 4; cc++) o[nb][cc] = 0.f;
    float l0 = 0.f, l1 = 0.f;
    const int gr0 = qbase + rq, gr1 = gr0 + 8;

    const int pkey = tid & 63, pdb = (tid >> 6) * 16;
    float4 vf[4];
    {
        const float4* vs = (const float4*)(V + ((size_t)(b * S_ + t0 * BN + pkey)) * D_ + pdb);
#pragma unroll
        for (int j = 0; j < 4; j++) vf[j] = vs[j];
    }

    for (int t = t0; t < t1; t++) {
        __syncthreads();   // prev MMA1/MMA2 done with KP/VP
        // ---- K: load + pack hi/lo; V: store prefetched ----
        {
            const float4* ks = (const float4*)(K + ((size_t)(b * S_ + t * BN + pkey)) * D_ + pdb);
            float4 kf[4];
#pragma unroll
            for (int j = 0; j < 4; j++) kf[j] = ks[j];
            float e[16];
#pragma unroll
            for (int j = 0; j < 4; j++) { e[4*j]=kf[j].x; e[4*j+1]=kf[j].y; e[4*j+2]=kf[j].z; e[4*j+3]=kf[j].w; }
            const int rot = (pkey >> 1) & 3;
#pragma unroll
            for (int cc = 0; cc < 2; cc++) {
                const int kc = (pdb >> 3) + cc;
#pragma unroll
                for (int j = 0; j < 4; j++) {
                    float h0f = e[cc*8 + j], h1f = e[cc*8 + j + 4];
                    u32 h0 = f2tf(h0f), h1 = f2tf(h1f);
                    u32 l0w = f2tf(h0f - __uint_as_float(h0));
                    u32 l1w = f2tf(h1f - __uint_as_float(h1));
                    *(uint4*)&sm[KP_O + kc*1024 + pkey*16 + (((j + rot) & 3) << 2)] =
                        make_uint4(h0, h1, l0w, l1w);
                }
            }
#pragma unroll
            for (int j = 0; j < 4; j++) { e[4*j]=vf[j].x; e[4*j+1]=vf[j].y; e[4*j+2]=vf[j].z; e[4*j+3]=vf[j].w; }
            const int kcv = pkey >> 3, tv = pkey & 3, sl = (pkey >> 2) & 1;
#pragma unroll
            for (int i = 0; i < 16; i++) {
                const int d = pdb + i;
                sm[VP_O + kcv*512 + d*8 + (((tv + (d >> 1)) & 3) << 1) + sl] = f2tf(e[i]);
            }
        }
        __syncthreads();   // tiles visible

        if (t + 1 < t1) {
            const float4* vs = (const float4*)(V + ((size_t)(b * S_ + (t+1) * BN + pkey)) * D_ + pdb);
#pragma unroll
            for (int j = 0; j < 4; j++) vf[j] = vs[j];
        }

        // ---- MMA1: S = Q @ K^T (3xtf32), this warp's 32-key half ----
        float s[4][4];
#pragma unroll
        for (int nb = 0; nb < 4; nb++)
#pragma unroll
            for (int cc = 0; cc < 4; cc++) s[nb][cc] = 0.f;
#pragma unroll
        for (int kc = 0; kc < 8; kc++) {
            uint4 qa = *(const uint4*)&sm[QP_O + kc*1024 + rq*16 + (sw << 2)];
            uint4 qc = *(const uint4*)&sm[QP_O + kc*1024 + (rq+8)*16 + (sw << 2)];
            u32 ah[4] = { qa.x, qc.x, qa.y, qc.y };
            u32 al[4] = { qa.z, qc.z, qa.w, qc.w };
#pragma unroll
            for (int nb = 0; nb < 4; nb++) {
                const int key = cw * 32 + nb * 8 + gid;
                uint4 kb = *(const uint4*)&sm[KP_O + kc*1024 + key*16 + (sw << 2)];
                mma8(s[nb], ah, kb.x, kb.y);
                mma8(s[nb], al, kb.x, kb.y);
                mma8(s[nb], ah, kb.z, kb.w);
            }
        }

        // ---- exp (+ causal mask on the diagonal tile), l accumulation ----
        const bool diag = (t == qb);
#pragma unroll
        for (int nb = 0; nb < 4; nb++) {
            const int cg = t * BN + cw * 32 + nb * 8 + 2 * tig;
            float p0, p1, p2, p3;
            if (diag) {
                p0 = (cg     <= gr0) ? __expf(s[nb][0]) : 0.f;
                p1 = (cg + 1 <= gr0) ? __expf(s[nb][1]) : 0.f;
                p2 = (cg     <= gr1) ? __expf(s[nb][2]) : 0.f;
                p3 = (cg + 1 <= gr1) ? __expf(s[nb][3]) : 0.f;
            } else {
                p0 = __expf(s[nb][0]); p1 = __expf(s[nb][1]);
                p2 = __expf(s[nb][2]); p3 = __expf(s[nb][3]);
            }
            l0 += p0 + p1;
            l1 += p2 + p3;
            s[nb][0] = p0; s[nb][1] = p1; s[nb][2] = p2; s[nb][3] = p3;
        }

        // ---- MMA2: O += P @ V over this key-half; P via shfl transpose ----
#pragma unroll
        for (int kc = 0; kc < 4; kc++) {
            u32 u0 = f2tf(s[kc][0]), u1 = f2tf(s[kc][1]);
            u32 u2 = f2tf(s[kc][2]), u3 = f2tf(s[kc][3]);
            u32 x0 = __shfl_sync(0xffffffffu, u0, srcA);
            u32 x1 = __shfl_sync(0xffffffffu, u1, srcA);
            u32 x2 = __shfl_sync(0xffffffffu, u2, srcA);
            u32 x3 = __shfl_sync(0xffffffffu, u3, srcA);
            u32 y0 = __shfl_sync(0xffffffffu, u0, srcB);
            u32 y1 = __shfl_sync(0xffffffffu, u1, srcB);
            u32 y2 = __shfl_sync(0xffffffffu, u2, srcB);
            u32 y3 = __shfl_sync(0xffffffffu, u3, srcB);
            u32 a[4];
            a[0] = comp ? x1 : x0;
            a[1] = comp ? x3 : x2;
            a[2] = comp ? y1 : y0;
            a[3] = comp ? y3 : y2;
            const int kcg = cw * 4 + kc;
#pragma unroll
            for (int nb = 0; nb < 8; nb++) {
                const int d = nb * 8 + gid;
                uint2 vb = *(const uint2*)&sm[VP_O + kcg*512 + d*8 + (sw << 1)];
                mma8(o[nb], a, vb.x, vb.y);
            }
        }
    }

    // ---- epilogue: atomic-combine partials ----
    l0 += __shfl_xor_sync(0xffffffffu, l0, 1);
    l0 += __shfl_xor_sync(0xffffffffu, l0, 2);
    l1 += __shfl_xor_sync(0xffffffffu, l1, 1);
    l1 += __shfl_xor_sync(0xffffffffu, l1, 2);
    if (tig == 0) {
        atomicAdd(&g_Lsum[b * S_ + gr0], l0);
        atomicAdd(&g_Lsum[b * S_ + gr1], l1);
    }
    float* og0 = O + ((size_t)(b * S_ + gr0)) * D_;
    float* og1 = O + ((size_t)(b * S_ + gr1)) * D_;
#pragma unroll
    for (int nb = 0; nb < 8; nb++) {
        const int col = nb * 8 + 2 * tig;
        atomicAdd(og0 + col,     o[nb][0]);
        atomicAdd(og0 + col + 1, o[nb][1]);
        atomicAdd(og1 + col,     o[nb][2]);
        atomicAdd(og1 + col + 1, o[nb][3]);
    }
}

extern "C" void kernel_launch(void* const* d_in, const int* in_sizes, int n_in,
                              void* d_out, int out_size) {
    const float* q = (const float*)d_in[0];
    const float* k = (const float*)d_in[1];
    const float* v = (const float*)d_in[2];
    float* o = (float*)d_out;
    const int n4 = (B_ * S_ * D_) / 4;   // 262144 float4
    cudaFuncSetAttribute(fa_chunk, cudaFuncAttributeMaxDynamicSharedMemorySize, SM_BYTES);
    zero_k<<<(n4 + 255) / 256, 256>>>(o, n4);
    dim3 grid(NCHUNK, B_);   // 80 x 8 = 640 chunk-CTAs
    fa_chunk<<<grid, NT, SM_BYTES>>>(q, k, v, o);
    norm_k<<<(n4 + 255) / 256, 256>>>(o, n4);
}

// round 14
// speedup vs baseline: 1.8274x; 1.0184x over previous
#include <cuda_runtime.h>
#include <math.h>
#include <stdint.h>

#define B_  8
#define S_  2048
#define D_  64
#define BM  64
#define BN  64
#define NT  256
#define CW  8           // kv tiles per chunk
#define NCHUNK 80       // chunks per batch

typedef uint32_t u32;

// smem word offsets
#define QP_O 0                    // [8kc][64r][4tig] uint4 (hi,hi+4,lo,lo+4)
#define KP_O (QP_O + 8192)
#define VP_O (KP_O + 8192)        // [8kcv][64d][8] packed uint2 (V[k],V[k+4])
#define KS_O (VP_O + 4096)        // raw K stage [16 granule][64 key][4w]
#define SM_WORDS (KS_O + 4096)
#define SM_BYTES (SM_WORDS * 4)   // 98304 B -> 2 CTAs/SM

__device__ float g_Lsum[B_ * S_];   // per-row partial softmax denominators

__device__ __forceinline__ u32 f2tf(float x) {
    u32 r; asm("cvt.rna.tf32.f32 %0, %1;" : "=r"(r) : "f"(x)); return r;
}
__device__ __forceinline__ u32 smem_u32(const void* p) {
    u32 a; asm("{ .reg .u64 t; cvta.to.shared.u64 t, %1; cvt.u32.u64 %0, t; }" : "=r"(a) : "l"(p));
    return a;
}
__device__ __forceinline__ void cpa16(u32 dst, const void* src) {
    asm volatile("cp.async.cg.shared.global [%0], [%1], 16;" :: "r"(dst), "l"(src) : "memory");
}
#define CPA_COMMIT() asm volatile("cp.async.commit_group;" ::: "memory")
#define CPA_WAIT()   asm volatile("cp.async.wait_group 0;" ::: "memory")

__device__ __forceinline__ void mma8(float* d, const u32* a, u32 b0, u32 b1) {
    asm volatile("mma.sync.aligned.m16n8k8.row.col.f32.tf32.tf32.f32 "
        "{%0,%1,%2,%3}, {%4,%5,%6,%7}, {%8,%9}, {%0,%1,%2,%3};"
        : "+f"(d[0]), "+f"(d[1]), "+f"(d[2]), "+f"(d[3])
        : "r"(a[0]), "r"(a[1]), "r"(a[2]), "r"(a[3]), "r"(b0), "r"(b1));
}

__global__ void zero_k(float* __restrict__ out, int n4) {
    int i = blockIdx.x * blockDim.x + threadIdx.x;
    if (i < n4) ((float4*)out)[i] = make_float4(0.f, 0.f, 0.f, 0.f);
    if (i < (B_ * S_) / 4) ((float4*)g_Lsum)[i] = make_float4(0.f, 0.f, 0.f, 0.f);
}

__global__ void norm_k(float* __restrict__ out, int n4) {
    int i = blockIdx.x * blockDim.x + threadIdx.x;
    if (i >= n4) return;
    float inv = 1.f / g_Lsum[i >> 4];
    float4 v = ((float4*)out)[i];
    v.x *= inv; v.y *= inv; v.z *= inv; v.w *= inv;
    ((float4*)out)[i] = v;
}

// Causal flash attention, mma.sync tf32 (3xtf32 QK^T, 1xtf32 PV), split-K chunks,
// cp.async-staged K (LDG latency off the per-tile critical path).
__global__ __launch_bounds__(NT, 2) void fa_chunk(
    const float* __restrict__ Q, const float* __restrict__ K,
    const float* __restrict__ V, float* __restrict__ O)
{
    extern __shared__ u32 sm[];
    const u32 sb = smem_u32(sm);
    const int tid  = threadIdx.x;
    const int lane = tid & 31;
    const int gid  = lane >> 2;
    const int tig  = lane & 3;
    const int rw   = (tid >> 5) >> 1;
    const int cw   = (tid >> 5) & 1;
    const int b    = blockIdx.y;

    // ---- decode (qb, chunk) ----
    int qb, c;
    {
        const int i = blockIdx.x;
        if (i < 8)       { qb = i; c = 0; }
        else if (i < 24) { int j = i - 8;  qb = 8  + (j >> 1); c = j & 1; }
        else if (i < 48) { int j = i - 24; qb = 16 + j / 3;    c = j - 3 * (j / 3); }
        else             { int j = i - 48; qb = 24 + (j >> 2); c = j & 3; }
    }
    const int t0 = c * CW;
    const int t1 = min(t0 + CW, qb + 1);
    const int qbase = qb * BM;
    const int rq   = rw * 16 + gid;
    const int sw   = (tig + (gid >> 1)) & 3;
    const int srcA = (lane & ~3) | (tig >> 1);
    const int srcB = srcA + 2;
    const u32 comp = tig & 1;

    const int pkey = tid & 63, pdb = (tid >> 6) * 16;
    const int g0 = pdb >> 2;   // first granule index (4 granules per thread)

    // ---- kick off K(t0) staging immediately ----
    {
        const float* ksrc = K + ((size_t)(b * S_ + t0 * BN + pkey)) * D_ + pdb;
#pragma unroll
        for (int j = 0; j < 4; j++)
            cpa16(sb + (KS_O + (g0 + j) * 256 + pkey * 4) * 4, ksrc + 4 * j);
        CPA_COMMIT();
    }

    // ---- Q -> QP packed hi/lo ----
    {
        const int qrow = tid & 63, db = (tid >> 6) * 16;
        const float4* src = (const float4*)(Q + ((size_t)(b * S_ + qbase + qrow)) * D_ + db);
        float e[16];
#pragma unroll
        for (int j = 0; j < 4; j++) { float4 x = src[j]; e[4*j]=x.x; e[4*j+1]=x.y; e[4*j+2]=x.z; e[4*j+3]=x.w; }
        const int rot = (qrow >> 1) & 3;
#pragma unroll
        for (int cc = 0; cc < 2; cc++) {
            const int kc = (db >> 3) + cc;
#pragma unroll
            for (int j = 0; j < 4; j++) {
                float h0f = e[cc*8 + j], h1f = e[cc*8 + j + 4];
                u32 h0 = f2tf(h0f), h1 = f2tf(h1f);
                u32 l0w = f2tf(h0f - __uint_as_float(h0));
                u32 l1w = f2tf(h1f - __uint_as_float(h1));
                *(uint4*)&sm[QP_O + kc*1024 + qrow*16 + (((j + rot) & 3) << 2)] =
                    make_uint4(h0, h1, l0w, l1w);
            }
        }
    }

    float o[8][4];
#pragma unroll
    for (int nb = 0; nb < 8; nb++)
#pragma unroll
        for (int cc = 0; cc < 4; cc++) o[nb][cc] = 0.f;
    float l0 = 0.f, l1 = 0.f;
    const int gr0 = qbase + rq, gr1 = gr0 + 8;

    float4 vf[4];
    {
        const float4* vs = (const float4*)(V + ((size_t)(b * S_ + t0 * BN + pkey)) * D_ + pdb);
#pragma unroll
        for (int j = 0; j < 4; j++) vf[j] = vs[j];
    }

    for (int t = t0; t < t1; t++) {
        // ---- read own staged K granules (no cross-thread visibility needed) ----
        CPA_WAIT();
        float4 kraw[4];
#pragma unroll
        for (int j = 0; j < 4; j++)
            kraw[j] = *(const float4*)&sm[KS_O + (g0 + j) * 256 + pkey * 4];

        __syncthreads();   // prev MMA1/MMA2 done with KP/VP
        // ---- convert staged K -> packed hi/lo; store prefetched V ----
        {
            float e[16];
#pragma unroll
            for (int j = 0; j < 4; j++) { e[4*j]=kraw[j].x; e[4*j+1]=kraw[j].y; e[4*j+2]=kraw[j].z; e[4*j+3]=kraw[j].w; }
            const int rot = (pkey >> 1) & 3;
#pragma unroll
            for (int cc = 0; cc < 2; cc++) {
                const int kc = (pdb >> 3) + cc;
#pragma unroll
                for (int j = 0; j < 4; j++) {
                    float h0f = e[cc*8 + j], h1f = e[cc*8 + j + 4];
                    u32 h0 = f2tf(h0f), h1 = f2tf(h1f);
                    u32 l0w = f2tf(h0f - __uint_as_float(h0));
                    u32 l1w = f2tf(h1f - __uint_as_float(h1));
                    *(uint4*)&sm[KP_O + kc*1024 + pkey*16 + (((j + rot) & 3) << 2)] =
                        make_uint4(h0, h1, l0w, l1w);
                }
            }
#pragma unroll
            for (int j = 0; j < 4; j++) { e[4*j]=vf[j].x; e[4*j+1]=vf[j].y; e[4*j+2]=vf[j].z; e[4*j+3]=vf[j].w; }
            const int kcv = pkey >> 3, tv = pkey & 3, sl = (pkey >> 2) & 1;
#pragma unroll
            for (int i = 0; i < 16; i++) {
                const int d = pdb + i;
                sm[VP_O + kcv*512 + d*8 + (((tv + (d >> 1)) & 3) << 1) + sl] = f2tf(e[i]);
            }
        }
        __syncthreads();   // tiles visible; stage reads complete -> safe to refill

        // ---- prefetch next K (cp.async) and V (regs), overlapping compute ----
        if (t + 1 < t1) {
            const float* ksrc = K + ((size_t)(b * S_ + (t+1) * BN + pkey)) * D_ + pdb;
#pragma unroll
            for (int j = 0; j < 4; j++)
                cpa16(sb + (KS_O + (g0 + j) * 256 + pkey * 4) * 4, ksrc + 4 * j);
            CPA_COMMIT();
            const float4* vs = (const float4*)(V + ((size_t)(b * S_ + (t+1) * BN + pkey)) * D_ + pdb);
#pragma unroll
            for (int j = 0; j < 4; j++) vf[j] = vs[j];
        }

        // ---- MMA1: S = Q @ K^T (3xtf32), this warp's 32-key half ----
        float s[4][4];
#pragma unroll
        for (int nb = 0; nb < 4; nb++)
#pragma unroll
            for (int cc = 0; cc < 4; cc++) s[nb][cc] = 0.f;
#pragma unroll
        for (int kc = 0; kc < 8; kc++) {
            uint4 qa = *(const uint4*)&sm[QP_O + kc*1024 + rq*16 + (sw << 2)];
            uint4 qc = *(const uint4*)&sm[QP_O + kc*1024 + (rq+8)*16 + (sw << 2)];
            u32 ah[4] = { qa.x, qc.x, qa.y, qc.y };
            u32 al[4] = { qa.z, qc.z, qa.w, qc.w };
#pragma unroll
            for (int nb = 0; nb < 4; nb++) {
                const int key = cw * 32 + nb * 8 + gid;
                uint4 kb = *(const uint4*)&sm[KP_O + kc*1024 + key*16 + (sw << 2)];
                mma8(s[nb], ah, kb.x, kb.y);
                mma8(s[nb], al, kb.x, kb.y);
                mma8(s[nb], ah, kb.z, kb.w);
            }
        }

        // ---- exp (+ causal mask on diagonal tile), l accumulation ----
        const bool diag = (t == qb);
#pragma unroll
        for (int nb = 0; nb < 4; nb++) {
            const int cg = t * BN + cw * 32 + nb * 8 + 2 * tig;
            float p0, p1, p2, p3;
            if (diag) {
                p0 = (cg     <= gr0) ? __expf(s[nb][0]) : 0.f;
                p1 = (cg + 1 <= gr0) ? __expf(s[nb][1]) : 0.f;
                p2 = (cg     <= gr1) ? __expf(s[nb][2]) : 0.f;
                p3 = (cg + 1 <= gr1) ? __expf(s[nb][3]) : 0.f;
            } else {
                p0 = __expf(s[nb][0]); p1 = __expf(s[nb][1]);
                p2 = __expf(s[nb][2]); p3 = __expf(s[nb][3]);
            }
            l0 += p0 + p1;
            l1 += p2 + p3;
            s[nb][0] = p0; s[nb][1] = p1; s[nb][2] = p2; s[nb][3] = p3;
        }

        // ---- MMA2: O += P @ V over this key-half; P via shfl transpose ----
#pragma unroll
        for (int kc = 0; kc < 4; kc++) {
            u32 u0 = f2tf(s[kc][0]), u1 = f2tf(s[kc][1]);
            u32 u2 = f2tf(s[kc][2]), u3 = f2tf(s[kc][3]);
            u32 x0 = __shfl_sync(0xffffffffu, u0, srcA);
            u32 x1 = __shfl_sync(0xffffffffu, u1, srcA);
            u32 x2 = __shfl_sync(0xffffffffu, u2, srcA);
            u32 x3 = __shfl_sync(0xffffffffu, u3, srcA);
            u32 y0 = __shfl_sync(0xffffffffu, u0, srcB);
            u32 y1 = __shfl_sync(0xffffffffu, u1, srcB);
            u32 y2 = __shfl_sync(0xffffffffu, u2, srcB);
            u32 y3 = __shfl_sync(0xffffffffu, u3, srcB);
            u32 a[4];
            a[0] = comp ? x1 : x0;
            a[1] = comp ? x3 : x2;
            a[2] = comp ? y1 : y0;
            a[3] = comp ? y3 : y2;
            const int kcg = cw * 4 + kc;
#pragma unroll
            for (int nb = 0; nb < 8; nb++) {
                const int d = nb * 8 + gid;
                uint2 vb = *(const uint2*)&sm[VP_O + kcg*512 + d*8 + (sw << 1)];
                mma8(o[nb], a, vb.x, vb.y);
            }
        }
    }

    // ---- epilogue: atomic-combine partials ----
    l0 += __shfl_xor_sync(0xffffffffu, l0, 1);
    l0 += __shfl_xor_sync(0xffffffffu, l0, 2);
    l1 += __shfl_xor_sync(0xffffffffu, l1, 1);
    l1 += __shfl_xor_sync(0xffffffffu, l1, 2);
    if (tig == 0) {
        atomicAdd(&g_Lsum[b * S_ + gr0], l0);
        atomicAdd(&g_Lsum[b * S_ + gr1], l1);
    }
    float* og0 = O + ((size_t)(b * S_ + gr0)) * D_;
    float* og1 = O + ((size_t)(b * S_ + gr1)) * D_;
#pragma unroll
    for (int nb = 0; nb < 8; nb++) {
        const int col = nb * 8 + 2 * tig;
        atomicAdd(og0 + col,     o[nb][0]);
        atomicAdd(og0 + col + 1, o[nb][1]);
        atomicAdd(og1 + col,     o[nb][2]);
        atomicAdd(og1 + col + 1, o[nb][3]);
    }
}

extern "C" void kernel_launch(void* const* d_in, const int* in_sizes, int n_in,
                              void* d_out, int out_size) {
    const float* q = (const float*)d_in[0];
    const float* k = (const float*)d_in[1];
    const float* v = (const float*)d_in[2];
    float* o = (float*)d_out;
    const int n4 = (B_ * S_ * D_) / 4;
    cudaFuncSetAttribute(fa_chunk, cudaFuncAttributeMaxDynamicSharedMemorySize, SM_BYTES);
    zero_k<<<(n4 + 255) / 256, 256>>>(o, n4);
    dim3 grid(NCHUNK, B_);   // 80 x 8 = 640 chunk-CTAs
    fa_chunk<<<grid, NT, SM_BYTES>>>(q, k, v, o);
    norm_k<<<(n4 + 255) / 256, 256>>>(o, n4);
}